// round 9
// baseline (speedup 1.0000x reference)
#include <cuda_runtime.h>
#include <cuda_fp16.h>
#include <cstdint>
#include <cstddef>

// ---------------------------------------------------------------------------
// Problem constants
// ---------------------------------------------------------------------------
#define NB     8
#define IN_CH  16
#define OUT_CH 32
#define GFC    64
#define EH     256
#define EW     320
#define OH     128
#define OW     160
#define EX2    64
#define HFULL2 256
#define WFULL2 320
#define XROWS  130
#define XCOLS  162
#define X1R    258
#define X1C    322

#define N_HID  ((size_t)NB*OUT_CH*OH*OW)
#define N_HC   ((size_t)NB*OUT_CH*HFULL2*WFULL2)
#define OFF_H  (N_HID)
#define OFF_C  (N_HID + N_HC)
#define OFF_GF (N_HID + 2*N_HC)

// conv2 smem layout (halves):
//   A halo: 204 pixels (6y x 34x) x 72 (64 ch + 8 pad)  = 14688 halves, 29376 B
//   B bufs: 2 x 128 oc x 72                             = 2 x 9216 halves
#define PXSTR   72
#define A_HALVES (204*PXSTR)         // 14688
#define A_BYTES  (A_HALVES*2)        // 29376
#define BBUF_HALVES (128*PXSTR)      // 9216
#define BBUF_BYTES  (BBUF_HALVES*2)  // 18432

// conv1 staging (halves)
#define C1STR    24
#define A1SLICE (128*C1STR)
#define B1SLICE (96*C1STR)
#define GSTR2 129

// ---------------------------------------------------------------------------
// Scratch
// ---------------------------------------------------------------------------
__device__ __half g_xin[NB*XROWS*XCOLS*64];   // NHWC conv2 input
__device__ __half g_x1[NB*X1R*X1C*16];        // NHWC conv1 input
__device__ __half g_wre[9*128*64];            // conv2 w [tap][oc][64ic]
__device__ __half g_w1[9*96*16];              // conv1 w [tap][oc][16ic]
__device__ float  g_gfsum[NB*GFC];
__device__ float  g_gfc[NB*96*4];

__device__ __forceinline__ float sigf(float x) { return 1.0f / (1.0f + expf(-x)); }

__device__ __forceinline__ uint32_t pack_h2(float a, float b) {
    __half2 h = __floats2half2_rn(a, b);
    return *reinterpret_cast<uint32_t*>(&h);
}
__device__ __forceinline__ uint32_t ldh2(const __half* p) {
    return *(const uint32_t*)p;
}
__device__ __forceinline__ uint32_t smem_u32(const void* p) {
    uint32_t a;
    asm("{ .reg .u64 t; cvta.to.shared.u64 t, %1; cvt.u32.u64 %0, t; }"
        : "=r"(a) : "l"(p));
    return a;
}
__device__ __forceinline__ void cp16(uint32_t dst, const void* src) {
    asm volatile("cp.async.cg.shared.global [%0], [%1], 16;"
                 :: "r"(dst), "l"(src) : "memory");
}
#define CP_COMMIT() asm volatile("cp.async.commit_group;" ::: "memory")
#define CP_WAIT1()  asm volatile("cp.async.wait_group 1;" ::: "memory")

// mma m16n8k16 fp16 -> fp32 accumulate
__device__ __forceinline__ void mma16816(float* c, const uint32_t* a, const uint32_t* b) {
    asm volatile(
        "mma.sync.aligned.m16n8k16.row.col.f32.f16.f16.f32 "
        "{%0,%1,%2,%3}, {%4,%5,%6,%7}, {%8,%9}, {%0,%1,%2,%3};"
        : "+f"(c[0]), "+f"(c[1]), "+f"(c[2]), "+f"(c[3])
        : "r"(a[0]), "r"(a[1]), "r"(a[2]), "r"(a[3]), "r"(b[0]), "r"(b[1]));
}

// ---------------------------------------------------------------------------
// prep: gf-broadcast conv contributions + zero gf sums
// ---------------------------------------------------------------------------
__global__ void prep_kernel(const float* __restrict__ gf, const float* __restrict__ w) {
    int idx = blockIdx.x * 256 + threadIdx.x;
    if (idx < NB*GFC) g_gfsum[idx] = 0.0f;
    if (idx >= NB*96*4) return;
    int v  = idx & 3;
    int oc = (idx >> 2) % 96;
    int b  = idx / (96*4);
    int ky0 = (v >> 1) & 1, kx0 = v & 1;
    float s = 0.0f;
    for (int c = 0; c < GFC; c++) {
        const float* wp = w + ((size_t)(oc*80) + IN_CH + c) * 9;
        float wsum = 0.0f;
        for (int ky = ky0; ky < 3; ky++)
            for (int kx = kx0; kx < 3; kx++)
                wsum += wp[ky*3 + kx];
        s += gf[b*GFC + c] * wsum;
    }
    g_gfc[idx] = s;
}

// ---------------------------------------------------------------------------
// conv2 weight reorder: g_wre[(tap*128+oc)*64 + ic] (ic over both halves)
// ---------------------------------------------------------------------------
__global__ void wre_kernel(const float* __restrict__ gw) {
    int i = blockIdx.x * 256 + threadIdx.x;
    if (i >= 9*128*64) return;
    int ic  = i & 63;
    int oc  = (i >> 6) & 127;
    int tap = i >> 13;
    g_wre[i] = __float2half_rn(gw[((size_t)oc*64 + ic)*9 + tap]);
}
__global__ void w1_kernel(const float* __restrict__ w) {
    int i = blockIdx.x * 256 + threadIdx.x;
    if (i >= 9*96*16) return;
    int ic  = i & 15;
    int oc  = (i >> 4) % 96;
    int tap = i / (96*16);
    g_w1[i] = __float2half_rn(w[((size_t)oc*80 + ic)*9 + tap]);
}

// ---------------------------------------------------------------------------
// g_xin border zeroing, ch 0..31
// ---------------------------------------------------------------------------
__global__ void border_kernel() {
    int i = blockIdx.x * 256 + threadIdx.x;
    if (i >= NB * 580) return;
    int pos = i % 580;
    int b = i / 580;
    int row, col;
    if      (pos < 162) { row = 0;   col = pos; }
    else if (pos < 324) { row = 129; col = pos - 162; }
    else if (pos < 452) { row = pos - 324 + 1; col = 0; }
    else                { row = pos - 452 + 1; col = 161; }
    uint4* p = (uint4*)&g_xin[(((size_t)b*XROWS + row)*XCOLS + col)*64];
    uint4 z = {0,0,0,0};
    p[0] = z; p[1] = z; p[2] = z; p[3] = z;
}

// ---------------------------------------------------------------------------
// prev_h window -> g_xin ch 32..63 (fp16)
// ---------------------------------------------------------------------------
__global__ void transpose_h(const float* __restrict__ prev_h) {
    __shared__ float sm[32*163];
    const int row = blockIdx.x;
    const int b = blockIdx.y;
    const int t = threadIdx.x;
    if (row == 0) {
        if (t < 162) {
            uint4* d = (uint4*)&g_xin[(((size_t)b*XROWS)*XCOLS + t)*64 + 32];
            uint4 z = {0,0,0,0};
            d[0] = z; d[1] = z; d[2] = z; d[3] = z;
        }
        return;
    }
    for (int i = t; i < 32*162; i += 256) {
        int ic = i / 162, col = i % 162;
        sm[ic*163 + col] = prev_h[(((size_t)b*OUT_CH + ic)*HFULL2 + row - 1)*WFULL2 + 63 + col];
    }
    __syncthreads();
    if (t < 162) {
        const int col = t;
        uint32_t h2[16];
        #pragma unroll
        for (int j = 0; j < 16; j++)
            h2[j] = pack_h2(sm[(2*j)*163 + col], sm[(2*j+1)*163 + col]);
        uint4* d = (uint4*)&g_xin[(((size_t)b*XROWS + row)*XCOLS + col)*64 + 32];
        d[0] = make_uint4(h2[0],  h2[1],  h2[2],  h2[3]);
        d[1] = make_uint4(h2[4],  h2[5],  h2[6],  h2[7]);
        d[2] = make_uint4(h2[8],  h2[9],  h2[10], h2[11]);
        d[3] = make_uint4(h2[12], h2[13], h2[14], h2[15]);
    }
}

// ---------------------------------------------------------------------------
// x NCHW -> g_x1 NHWC padded (fp16), float4 loads. Grid (256, NB), 320 thr.
// ---------------------------------------------------------------------------
__global__ void xt_kernel(const float* __restrict__ x) {
    __shared__ float sm[16*321];
    const int gy = blockIdx.x;
    const int b = blockIdx.y;
    const int t = threadIdx.x;
    for (int i = t; i < 16*80; i += 320) {
        int ic = i / 80, g4 = (i % 80) * 4;
        float4 v = *(const float4*)&x[(((size_t)b*16 + ic)*EH + gy)*EW + g4];
        float* s = &sm[ic*321 + g4];
        s[0] = v.x; s[1] = v.y; s[2] = v.z; s[3] = v.w;
    }
    __syncthreads();
    __half* rowp = g_x1 + ((size_t)b*X1R + gy + 1)*X1C*16;
    {
        const int gx = t;
        uint32_t h2[8];
        #pragma unroll
        for (int j = 0; j < 8; j++)
            h2[j] = pack_h2(sm[(2*j)*321 + gx], sm[(2*j+1)*321 + gx]);
        uint4* d = (uint4*)(rowp + (size_t)(gx + 1)*16);
        d[0] = make_uint4(h2[0], h2[1], h2[2], h2[3]);
        d[1] = make_uint4(h2[4], h2[5], h2[6], h2[7]);
    }
    if (t == 0) {
        uint4* d = (uint4*)rowp;
        uint4 z = {0,0,0,0};
        d[0] = z; d[1] = z;
    }
    if (gy == 0) {
        uint4* r0 = (uint4*)(g_x1 + (size_t)b*X1R*X1C*16);
        uint4 z = {0,0,0,0};
        for (int i = t; i < X1C*16/8; i += 320) r0[i] = z;
    }
}

// ---------------------------------------------------------------------------
// conv1 implicit GEMM fp16 (unchanged, passing): M=128, N=96, K=144
// ---------------------------------------------------------------------------
__device__ __forceinline__ void load_slice1(int s, uint32_t ab, uint32_t bb,
                                            const __half* x1_b, int y0, int x0, int tid) {
    const int ky = s / 3, kx = s - 3*ky;
    {
        int r = tid >> 1, c = tid & 1;
        int y = y0 + (r >> 5), x = x0 + (r & 31);
        const __half* src = x1_b + ((size_t)(2*y + ky)*X1C + (2*x + kx))*16 + c*8;
        cp16(ab + (uint32_t)(r*(C1STR*2) + c*16), src);
    }
    if (tid < 192) {
        int r = tid >> 1, c = tid & 1;
        const __half* src = g_w1 + (size_t)s*1536 + r*16 + c*8;
        cp16(bb + (uint32_t)(r*(C1STR*2) + c*16), src);
    }
}

__global__ __launch_bounds__(256) void conv1_mma(const float* __restrict__ cb) {
    extern __shared__ __align__(16) float smem[];
    __half* hb = (__half*)smem;
    float* gates1 = smem;

    const uint32_t su = smem_u32(smem);
    const int tid = threadIdx.x;
    const int lane = tid & 31, wid = tid >> 5;
    const int warp_m = wid & 3, warp_n = wid >> 2;
    const int tile = blockIdx.x, b = blockIdx.y;
    const int y0 = (tile / 5) * 4, x0 = (tile % 5) * 32;

    const __half* x1_b = g_x1 + (size_t)b * X1R * X1C * 16;

    float acc[2][6][4] = {};

    load_slice1(0, su,        su + 12288, x1_b, y0, x0, tid); CP_COMMIT();
    load_slice1(1, su + 6144, su + 16896, x1_b, y0, x0, tid); CP_COMMIT();

    const int qr = lane >> 2, qc = lane & 3;

    for (int s = 0; s < 9; s++) {
        const int buf = s & 1;
        CP_WAIT1();
        __syncthreads();

        const __half* Ah = hb + buf*A1SLICE + warp_m*32*C1STR;
        const __half* Bh = hb + 2*A1SLICE + buf*B1SLICE + warp_n*48*C1STR;

        uint32_t af[2][4], bf[6][2];
        #pragma unroll
        for (int mt = 0; mt < 2; mt++) {
            const __half* ap = Ah + (mt*16 + qr)*C1STR + 2*qc;
            af[mt][0] = ldh2(ap);
            af[mt][1] = ldh2(ap + 8*C1STR);
            af[mt][2] = ldh2(ap + 8);
            af[mt][3] = ldh2(ap + 8*C1STR + 8);
        }
        #pragma unroll
        for (int nt = 0; nt < 6; nt++) {
            const __half* bp = Bh + (nt*8 + qr)*C1STR + 2*qc;
            bf[nt][0] = ldh2(bp);
            bf[nt][1] = ldh2(bp + 8);
        }
        #pragma unroll
        for (int mt = 0; mt < 2; mt++)
            #pragma unroll
            for (int nt = 0; nt < 6; nt++)
                mma16816(acc[mt][nt], af[mt], bf[nt]);

        __syncthreads();
        if (s + 2 < 9)
            load_slice1(s + 2, su + buf*6144, su + 12288 + buf*4608,
                        x1_b, y0, x0, tid);
        CP_COMMIT();
    }

    __syncthreads();
    #pragma unroll
    for (int mt = 0; mt < 2; mt++) {
        int m = warp_m*32 + mt*16 + qr;
        #pragma unroll
        for (int nt = 0; nt < 6; nt++) {
            int n = warp_n*48 + nt*8 + 2*qc;
            gates1[(size_t)n*GSTR2 + m]         = acc[mt][nt][0];
            gates1[(size_t)(n+1)*GSTR2 + m]     = acc[mt][nt][1];
            gates1[(size_t)n*GSTR2 + m + 8]     = acc[mt][nt][2];
            gates1[(size_t)(n+1)*GSTR2 + m + 8] = acc[mt][nt][3];
        }
    }
    __syncthreads();

    if (tid < 128) {
        const int m = tid;
        const int y = y0 + (m >> 5), x = x0 + (m & 31);
        const int v = ((y == 0) ? 2 : 0) | ((x == 0) ? 1 : 0);
        float vals[32];
        #pragma unroll
        for (int n = 0; n < 32; n++)
            vals[n] = tanhf(gates1[(size_t)n*GSTR2 + m] + cb[n]
                            + g_gfc[(b*96 + n)*4 + v]);
        uint32_t h2[16];
        #pragma unroll
        for (int j = 0; j < 16; j++) h2[j] = pack_h2(vals[2*j], vals[2*j+1]);
        uint4* d = (uint4*)&g_xin[(((size_t)b*XROWS + y + 1)*XCOLS + x + 1)*64];
        d[0] = make_uint4(h2[0],  h2[1],  h2[2],  h2[3]);
        d[1] = make_uint4(h2[4],  h2[5],  h2[6],  h2[7]);
        d[2] = make_uint4(h2[8],  h2[9],  h2[10], h2[11]);
        d[3] = make_uint4(h2[12], h2[13], h2[14], h2[15]);
    } else {
        const int idx = tid - 128;
        const int n = 32 + (idx >> 1);
        const int mh = idx & 1;
        const float bn = cb[n];
        const float* gfc_n = &g_gfc[(b*96 + n)*4];
        float sum = 0.0f;
        #pragma unroll 8
        for (int mi = 0; mi < 64; mi++) {
            int m = mh*64 + mi;
            int y = y0 + (m >> 5), x = x0 + (m & 31);
            int v = ((y == 0) ? 2 : 0) | ((x == 0) ? 1 : 0);
            sum += tanhf(gates1[(size_t)n*GSTR2 + m] + bn + gfc_n[v]);
        }
        atomicAdd(&g_gfsum[b*GFC + (n - 32)], sum);
    }
}

// ---------------------------------------------------------------------------
// new_gf
// ---------------------------------------------------------------------------
__global__ void gf_kernel(const float* __restrict__ gf, float* __restrict__ out) {
    int i = threadIdx.x;
    out[OFF_GF + i] = tanhf(gf[i] + g_gfsum[i] * (1.0f / (float)(OH*OW)));
}

// ---------------------------------------------------------------------------
// copy prev_h/prev_c -> out, skipping the interior region conv2 overwrites
// ---------------------------------------------------------------------------
__global__ void copy_hc(const float* __restrict__ ph, const float* __restrict__ pc,
                        float* __restrict__ out) {
    const int row = blockIdx.x;
    const int plane = blockIdx.y;
    const int t = threadIdx.x;
    if (t >= 80) return;
    if (row < 128 && t >= 16 && t < 56) return;
    size_t off = ((size_t)plane*HFULL2 + row)*WFULL2 + t*4;
    float4 vh = *(const float4*)(ph + off);
    float4 vc = *(const float4*)(pc + off);
    *(float4*)(out + OFF_H + off) = vh;
    *(float4*)(out + OFF_C + off) = vc;
}

// ---------------------------------------------------------------------------
// conv2: halo-resident implicit GEMM fp16 + fused LSTM epilogue.
// A halo (6x34 px x 64ch) loaded ONCE; 9 tap-stages of K=64 with
// double-buffered weights. Grid (160, NB), 256 thr.
// ---------------------------------------------------------------------------
__device__ __forceinline__ void load_A_halo(uint32_t su, const __half* xin_b,
                                            int y0, int x0, int tid) {
    #pragma unroll
    for (int i = 0; i < 7; i++) {
        int idx = tid + 256*i;
        if (idx < 1632) {                       // 204 pixels x 8 chunks
            int p = idx >> 3, c = idx & 7;
            int py = p / 34, px = p % 34;
            const __half* src = xin_b + ((size_t)(y0 + py)*XCOLS + (x0 + px))*64 + c*8;
            cp16(su + (uint32_t)(p*(PXSTR*2) + c*16), src);
        }
    }
}
__device__ __forceinline__ void load_B_tap(int tap, uint32_t bb, int tid) {
    const __half* gw = g_wre + (size_t)tap * 8192;
    #pragma unroll
    for (int i = 0; i < 4; i++) {
        int idx = tid + 256*i;                  // < 1024 = 128 oc x 8 chunks
        int r = idx >> 3, c = idx & 7;
        cp16(bb + (uint32_t)(r*(PXSTR*2) + c*16), gw + r*64 + c*8);
    }
}

__global__ __launch_bounds__(256) void conv2_mma(
    const float* __restrict__ prev_c, const float* __restrict__ gb,
    float* __restrict__ out)
{
    extern __shared__ __align__(16) float smem[];
    __half* hb = (__half*)smem;
    float* gates_s = smem;
    __shared__ float bias_s[128];

    const uint32_t su = smem_u32(smem);
    const int tid = threadIdx.x;
    const int lane = tid & 31, wid = tid >> 5;
    const int warp_m = wid & 3, warp_n = wid >> 2;
    const int tile = blockIdx.x, b = blockIdx.y;
    const int y0 = (tile / 5) * 4, x0 = (tile % 5) * 32;

    if (tid < 128) bias_s[tid] = gb[tid];

    const __half* xin_b = g_xin + (size_t)b * XROWS * XCOLS * 64;

    float acc[2][8][4] = {};

    // prologue: A halo + B tap0 in group 0; B tap1 in group 1
    load_A_halo(su, xin_b, y0, x0, tid);
    load_B_tap(0, su + A_BYTES, tid);               CP_COMMIT();
    load_B_tap(1, su + A_BYTES + BBUF_BYTES, tid);  CP_COMMIT();

    const int qr = lane >> 2, qc = lane & 3;
    // per-thread pixel bases (mt = 0,1): m = warp_m*32 + mt*16 + qr
    const int apix0 = warp_m*34 + qr;          // y=warp_m, x=qr
    const int apix1 = warp_m*34 + 16 + qr;     // y=warp_m, x=16+qr

    for (int tap = 0; tap < 9; tap++) {
        const int buf = tap & 1;
        CP_WAIT1();
        __syncthreads();

        const int shift = ((tap/3)*34 + (tap%3)) * PXSTR;
        const __half* A0 = hb + apix0*PXSTR + shift + 2*qc;
        const __half* A1 = hb + apix1*PXSTR + shift + 2*qc;
        const __half* Bh = hb + A_HALVES + buf*BBUF_HALVES + warp_n*64*PXSTR + 2*qc;

        #pragma unroll
        for (int kc = 0; kc < 4; kc++) {
            uint32_t af[2][4], bf[8][2];
            {
                const __half* ap = A0 + kc*16;
                af[0][0] = ldh2(ap);
                af[0][1] = ldh2(ap + 8*PXSTR);
                af[0][2] = ldh2(ap + 8);
                af[0][3] = ldh2(ap + 8*PXSTR + 8);
            }
            {
                const __half* ap = A1 + kc*16;
                af[1][0] = ldh2(ap);
                af[1][1] = ldh2(ap + 8*PXSTR);
                af[1][2] = ldh2(ap + 8);
                af[1][3] = ldh2(ap + 8*PXSTR + 8);
            }
            #pragma unroll
            for (int nt = 0; nt < 8; nt++) {
                const __half* bp = Bh + (nt*8 + qr)*PXSTR + kc*16;
                bf[nt][0] = ldh2(bp);
                bf[nt][1] = ldh2(bp + 8);
            }
            #pragma unroll
            for (int mt = 0; mt < 2; mt++)
                #pragma unroll
                for (int nt = 0; nt < 8; nt++)
                    mma16816(acc[mt][nt], af[mt], bf[nt]);
        }

        __syncthreads();
        if (tap + 2 < 9)
            load_B_tap(tap + 2, su + A_BYTES + buf*BBUF_BYTES, tid);
        CP_COMMIT();
    }

    // ---- epilogue: accums -> smem [n][m], fused LSTM ----
    __syncthreads();
    #pragma unroll
    for (int mt = 0; mt < 2; mt++) {
        int m = warp_m*32 + mt*16 + qr;
        #pragma unroll
        for (int nt = 0; nt < 8; nt++) {
            int n = warp_n*64 + nt*8 + 2*qc;
            gates_s[(size_t)n*GSTR2 + m]         = acc[mt][nt][0];
            gates_s[(size_t)(n+1)*GSTR2 + m]     = acc[mt][nt][1];
            gates_s[(size_t)n*GSTR2 + m + 8]     = acc[mt][nt][2];
            gates_s[(size_t)(n+1)*GSTR2 + m + 8] = acc[mt][nt][3];
        }
    }
    __syncthreads();

    if (tid < 128) {
        const int m = tid;
        const int y = y0 + (m >> 5), x = x0 + (m & 31);
        #pragma unroll
        for (int j = 0; j < 32; j++) {
            float ig = gates_s[(size_t)(j     )*GSTR2 + m] + bias_s[j];
            float rg = gates_s[(size_t)(j + 32)*GSTR2 + m] + bias_s[32 + j];
            float og = gates_s[(size_t)(j + 64)*GSTR2 + m] + bias_s[64 + j];
            float cg = gates_s[(size_t)(j + 96)*GSTR2 + m] + bias_s[96 + j];
            size_t hc = (((size_t)b*OUT_CH + j)*HFULL2 + y)*WFULL2 + EX2 + x;
            float pc = prev_c[hc];
            float cell = sigf(rg)*pc + sigf(ig)*tanhf(cg);
            float hid  = sigf(og)*tanhf(cell);
            out[(((size_t)b*OUT_CH + j)*OH + y)*OW + x] = hid;
            out[OFF_H + hc] = hid;
            out[OFF_C + hc] = cell;
        }
    }
}

// ---------------------------------------------------------------------------
// Launch
// ---------------------------------------------------------------------------
extern "C" void kernel_launch(void* const* d_in, const int* in_sizes, int n_in,
                              void* d_out, int out_size) {
    const float* x       = (const float*)d_in[0];
    const float* prev_h  = (const float*)d_in[1];
    const float* prev_c  = (const float*)d_in[2];
    const float* gf      = (const float*)d_in[3];
    const float* conv_w  = (const float*)d_in[4];
    const float* conv_b  = (const float*)d_in[5];
    const float* gates_w = (const float*)d_in[6];
    const float* gates_b = (const float*)d_in[7];
    float* out = (float*)d_out;

    const int stage2 = A_BYTES + 2*BBUF_BYTES;                    // 66240
    const int gates2 = 128 * GSTR2 * (int)sizeof(float);          // 66048
    const int smem2 = stage2 > gates2 ? stage2 : gates2;          // 66240
    const int smem1 = 96 * GSTR2 * (int)sizeof(float);            // 49536
    cudaFuncSetAttribute(conv2_mma, cudaFuncAttributeMaxDynamicSharedMemorySize, smem2);
    cudaFuncSetAttribute(conv1_mma, cudaFuncAttributeMaxDynamicSharedMemorySize, smem1);

    prep_kernel<<<(NB*96*4 + 255)/256, 256>>>(gf, conv_w);
    wre_kernel<<<(9*128*64 + 255)/256, 256>>>(gates_w);
    w1_kernel<<<(9*96*16 + 255)/256, 256>>>(conv_w);
    xt_kernel<<<dim3(EH, NB), 320>>>(x);
    transpose_h<<<dim3(XROWS, NB), 256>>>(prev_h);
    border_kernel<<<(NB*580 + 255)/256, 256>>>();

    conv1_mma<<<dim3(160, NB), 256, smem1>>>(conv_b);

    gf_kernel<<<1, NB*GFC>>>(gf, out);

    copy_hc<<<dim3(HFULL2, NB*OUT_CH), 128>>>(prev_h, prev_c, out);

    conv2_mma<<<dim3(160, NB), 256, smem2>>>(prev_c, gates_b, out);
}

// round 10
// speedup vs baseline: 1.2247x; 1.2247x over previous
#include <cuda_runtime.h>
#include <cuda_fp16.h>
#include <cstdint>
#include <cstddef>

// ---------------------------------------------------------------------------
// Problem constants
// ---------------------------------------------------------------------------
#define NB     8
#define IN_CH  16
#define OUT_CH 32
#define GFC    64
#define EH     256
#define EW     320
#define OH     128
#define OW     160
#define EX2    64
#define HFULL2 256
#define WFULL2 320
#define XROWS  130
#define XCOLS  162
#define X1R    258
#define X1C    322

#define N_HID  ((size_t)NB*OUT_CH*OH*OW)
#define N_HC   ((size_t)NB*OUT_CH*HFULL2*WFULL2)
#define OFF_H  (N_HID)
#define OFF_C  (N_HID + N_HC)
#define OFF_GF (N_HID + 2*N_HC)

// conv2 staging (halves): per-slice buffer = A(128px x 40) + B(128oc x 40)
#define C2STR   40
#define SLICEBUF_B 20480          // bytes: 10240 A + 10240 B
// conv1 staging (halves)
#define C1STR    24
#define A1SLICE (128*C1STR)
#define B1SLICE (96*C1STR)
#define GSTR2 129

// ---------------------------------------------------------------------------
// Scratch
// ---------------------------------------------------------------------------
__device__ __half g_xin[NB*XROWS*XCOLS*64];   // NHWC conv2 input
__device__ __half g_x1[NB*X1R*X1C*16];        // NHWC conv1 input
__device__ __half g_wre[18*128*32];           // conv2 w [slice][oc][32ic]
__device__ __half g_w1[9*96*16];              // conv1 w [tap][oc][16ic]
__device__ float  g_gfsum[NB*GFC];
__device__ float  g_gfc[NB*96*4];

__device__ __forceinline__ float sigf(float x) { return 1.0f / (1.0f + expf(-x)); }

__device__ __forceinline__ uint32_t pack_h2(float a, float b) {
    __half2 h = __floats2half2_rn(a, b);
    return *reinterpret_cast<uint32_t*>(&h);
}
__device__ __forceinline__ uint32_t ldh2(const __half* p) {
    return *(const uint32_t*)p;
}
__device__ __forceinline__ uint32_t smem_u32(const void* p) {
    uint32_t a;
    asm("{ .reg .u64 t; cvta.to.shared.u64 t, %1; cvt.u32.u64 %0, t; }"
        : "=r"(a) : "l"(p));
    return a;
}
__device__ __forceinline__ void cp16(uint32_t dst, const void* src) {
    asm volatile("cp.async.cg.shared.global [%0], [%1], 16;"
                 :: "r"(dst), "l"(src) : "memory");
}
#define CP_COMMIT() asm volatile("cp.async.commit_group;" ::: "memory")
#define CP_WAIT1()  asm volatile("cp.async.wait_group 1;" ::: "memory")
#define CP_WAIT2()  asm volatile("cp.async.wait_group 2;" ::: "memory")

// mma m16n8k16 fp16 -> fp32 accumulate
__device__ __forceinline__ void mma16816(float* c, const uint32_t* a, const uint32_t* b) {
    asm volatile(
        "mma.sync.aligned.m16n8k16.row.col.f32.f16.f16.f32 "
        "{%0,%1,%2,%3}, {%4,%5,%6,%7}, {%8,%9}, {%0,%1,%2,%3};"
        : "+f"(c[0]), "+f"(c[1]), "+f"(c[2]), "+f"(c[3])
        : "r"(a[0]), "r"(a[1]), "r"(a[2]), "r"(a[3]), "r"(b[0]), "r"(b[1]));
}

// ---------------------------------------------------------------------------
// prep_all: role by blockIdx.y
//   0: gf contributions + gfsum zero ; 1: conv2 weight reorder ;
//   2: conv1 weight reorder          ; 3: g_xin ch0..31 border zero
// ---------------------------------------------------------------------------
__global__ void prep_all(const float* __restrict__ gf, const float* __restrict__ w,
                         const float* __restrict__ gw) {
    const int role = blockIdx.y;
    const int idx = blockIdx.x * 256 + threadIdx.x;
    if (role == 0) {
        if (idx < NB*GFC) g_gfsum[idx] = 0.0f;
        if (idx >= NB*96*4) return;
        int v  = idx & 3;
        int oc = (idx >> 2) % 96;
        int b  = idx / (96*4);
        int ky0 = (v >> 1) & 1, kx0 = v & 1;
        float s = 0.0f;
        for (int c = 0; c < GFC; c++) {
            const float* wp = w + ((size_t)(oc*80) + IN_CH + c) * 9;
            float wsum = 0.0f;
            for (int ky = ky0; ky < 3; ky++)
                for (int kx = kx0; kx < 3; kx++)
                    wsum += wp[ky*3 + kx];
            s += gf[b*GFC + c] * wsum;
        }
        g_gfc[idx] = s;
    } else if (role == 1) {
        if (idx >= 18*128*32) return;
        int icl = idx & 31;
        int oc  = (idx >> 5) & 127;
        int s   = idx >> 12;
        int tap = s >> 1, h = s & 1;
        g_wre[idx] = __float2half_rn(gw[((size_t)oc*64 + h*32 + icl)*9 + tap]);
    } else if (role == 2) {
        if (idx >= 9*96*16) return;
        int ic  = idx & 15;
        int oc  = (idx >> 4) % 96;
        int tap = idx / (96*16);
        g_w1[idx] = __float2half_rn(w[((size_t)oc*80 + ic)*9 + tap]);
    } else {
        if (idx >= NB * 580) return;
        int pos = idx % 580;
        int b = idx / 580;
        int row, col;
        if      (pos < 162) { row = 0;   col = pos; }
        else if (pos < 324) { row = 129; col = pos - 162; }
        else if (pos < 452) { row = pos - 324 + 1; col = 0; }
        else                { row = pos - 452 + 1; col = 161; }
        uint4* p = (uint4*)&g_xin[(((size_t)b*XROWS + row)*XCOLS + col)*64];
        uint4 z = {0,0,0,0};
        p[0] = z; p[1] = z; p[2] = z; p[3] = z;
    }
}

// ---------------------------------------------------------------------------
// transforms: role by blockIdx.z
//   0: x NCHW -> g_x1 NHWC padded     (row gy = blockIdx.x, 0..255)
//   1: prev_h -> g_xin ch32..63 NHWC  (row = blockIdx.x, 0..129)
// Grid (256, NB, 2), 320 threads.
// ---------------------------------------------------------------------------
__global__ void transforms(const float* __restrict__ x, const float* __restrict__ prev_h) {
    __shared__ float sm[32*163];
    const int b = blockIdx.y;
    const int t = threadIdx.x;
    if (blockIdx.z == 0) {
        const int gy = blockIdx.x;
        for (int i = t; i < 16*80; i += 320) {
            int ic = i / 80, g4 = (i % 80) * 4;
            float4 v = *(const float4*)&x[(((size_t)b*16 + ic)*EH + gy)*EW + g4];
            float* s = &sm[ic*321 + g4];
            s[0] = v.x; s[1] = v.y; s[2] = v.z; s[3] = v.w;
        }
        __syncthreads();
        __half* rowp = g_x1 + ((size_t)b*X1R + gy + 1)*X1C*16;
        {
            const int gx = t;
            uint32_t h2[8];
            #pragma unroll
            for (int j = 0; j < 8; j++)
                h2[j] = pack_h2(sm[(2*j)*321 + gx], sm[(2*j+1)*321 + gx]);
            uint4* d = (uint4*)(rowp + (size_t)(gx + 1)*16);
            d[0] = make_uint4(h2[0], h2[1], h2[2], h2[3]);
            d[1] = make_uint4(h2[4], h2[5], h2[6], h2[7]);
        }
        if (t == 0) {
            uint4* d = (uint4*)rowp;
            uint4 z = {0,0,0,0};
            d[0] = z; d[1] = z;
        }
        if (gy == 0) {
            uint4* r0 = (uint4*)(g_x1 + (size_t)b*X1R*X1C*16);
            uint4 z = {0,0,0,0};
            for (int i = t; i < X1C*16/8; i += 320) r0[i] = z;
        }
    } else {
        const int row = blockIdx.x;
        if (row >= XROWS) return;
        if (row == 0) {
            if (t < 162) {
                uint4* d = (uint4*)&g_xin[(((size_t)b*XROWS)*XCOLS + t)*64 + 32];
                uint4 z = {0,0,0,0};
                d[0] = z; d[1] = z; d[2] = z; d[3] = z;
            }
            return;
        }
        for (int i = t; i < 32*162; i += 320) {
            int ic = i / 162, col = i % 162;
            sm[ic*163 + col] = prev_h[(((size_t)b*OUT_CH + ic)*HFULL2 + row - 1)*WFULL2 + 63 + col];
        }
        __syncthreads();
        if (t < 162) {
            const int col = t;
            uint32_t h2[16];
            #pragma unroll
            for (int j = 0; j < 16; j++)
                h2[j] = pack_h2(sm[(2*j)*163 + col], sm[(2*j+1)*163 + col]);
            uint4* d = (uint4*)&g_xin[(((size_t)b*XROWS + row)*XCOLS + col)*64 + 32];
            d[0] = make_uint4(h2[0],  h2[1],  h2[2],  h2[3]);
            d[1] = make_uint4(h2[4],  h2[5],  h2[6],  h2[7]);
            d[2] = make_uint4(h2[8],  h2[9],  h2[10], h2[11]);
            d[3] = make_uint4(h2[12], h2[13], h2[14], h2[15]);
        }
    }
}

// ---------------------------------------------------------------------------
// conv1 implicit GEMM fp16 (R8-proven): M=128, N=96, K=144
// ---------------------------------------------------------------------------
__device__ __forceinline__ void load_slice1(int s, uint32_t ab, uint32_t bb,
                                            const __half* x1_b, int y0, int x0, int tid) {
    const int ky = s / 3, kx = s - 3*ky;
    {
        int r = tid >> 1, c = tid & 1;
        int y = y0 + (r >> 5), x = x0 + (r & 31);
        const __half* src = x1_b + ((size_t)(2*y + ky)*X1C + (2*x + kx))*16 + c*8;
        cp16(ab + (uint32_t)(r*(C1STR*2) + c*16), src);
    }
    if (tid < 192) {
        int r = tid >> 1, c = tid & 1;
        const __half* src = g_w1 + (size_t)s*1536 + r*16 + c*8;
        cp16(bb + (uint32_t)(r*(C1STR*2) + c*16), src);
    }
}

__global__ __launch_bounds__(256) void conv1_mma(const float* __restrict__ cb) {
    extern __shared__ __align__(16) float smem[];
    __half* hb = (__half*)smem;
    float* gates1 = smem;

    const uint32_t su = smem_u32(smem);
    const int tid = threadIdx.x;
    const int lane = tid & 31, wid = tid >> 5;
    const int warp_m = wid & 3, warp_n = wid >> 2;
    const int tile = blockIdx.x, b = blockIdx.y;
    const int y0 = (tile / 5) * 4, x0 = (tile % 5) * 32;

    const __half* x1_b = g_x1 + (size_t)b * X1R * X1C * 16;

    float acc[2][6][4] = {};

    load_slice1(0, su,        su + 12288, x1_b, y0, x0, tid); CP_COMMIT();
    load_slice1(1, su + 6144, su + 16896, x1_b, y0, x0, tid); CP_COMMIT();

    const int qr = lane >> 2, qc = lane & 3;

    for (int s = 0; s < 9; s++) {
        const int buf = s & 1;
        CP_WAIT1();
        __syncthreads();

        const __half* Ah = hb + buf*A1SLICE + warp_m*32*C1STR;
        const __half* Bh = hb + 2*A1SLICE + buf*B1SLICE + warp_n*48*C1STR;

        uint32_t af[2][4], bf[6][2];
        #pragma unroll
        for (int mt = 0; mt < 2; mt++) {
            const __half* ap = Ah + (mt*16 + qr)*C1STR + 2*qc;
            af[mt][0] = ldh2(ap);
            af[mt][1] = ldh2(ap + 8*C1STR);
            af[mt][2] = ldh2(ap + 8);
            af[mt][3] = ldh2(ap + 8*C1STR + 8);
        }
        #pragma unroll
        for (int nt = 0; nt < 6; nt++) {
            const __half* bp = Bh + (nt*8 + qr)*C1STR + 2*qc;
            bf[nt][0] = ldh2(bp);
            bf[nt][1] = ldh2(bp + 8);
        }
        #pragma unroll
        for (int mt = 0; mt < 2; mt++)
            #pragma unroll
            for (int nt = 0; nt < 6; nt++)
                mma16816(acc[mt][nt], af[mt], bf[nt]);

        __syncthreads();
        if (s + 2 < 9)
            load_slice1(s + 2, su + buf*6144, su + 12288 + buf*4608,
                        x1_b, y0, x0, tid);
        CP_COMMIT();
    }

    __syncthreads();
    #pragma unroll
    for (int mt = 0; mt < 2; mt++) {
        int m = warp_m*32 + mt*16 + qr;
        #pragma unroll
        for (int nt = 0; nt < 6; nt++) {
            int n = warp_n*48 + nt*8 + 2*qc;
            gates1[(size_t)n*GSTR2 + m]         = acc[mt][nt][0];
            gates1[(size_t)(n+1)*GSTR2 + m]     = acc[mt][nt][1];
            gates1[(size_t)n*GSTR2 + m + 8]     = acc[mt][nt][2];
            gates1[(size_t)(n+1)*GSTR2 + m + 8] = acc[mt][nt][3];
        }
    }
    __syncthreads();

    if (tid < 128) {
        const int m = tid;
        const int y = y0 + (m >> 5), x = x0 + (m & 31);
        const int v = ((y == 0) ? 2 : 0) | ((x == 0) ? 1 : 0);
        float vals[32];
        #pragma unroll
        for (int n = 0; n < 32; n++)
            vals[n] = tanhf(gates1[(size_t)n*GSTR2 + m] + cb[n]
                            + g_gfc[(b*96 + n)*4 + v]);
        uint32_t h2[16];
        #pragma unroll
        for (int j = 0; j < 16; j++) h2[j] = pack_h2(vals[2*j], vals[2*j+1]);
        uint4* d = (uint4*)&g_xin[(((size_t)b*XROWS + y + 1)*XCOLS + x + 1)*64];
        d[0] = make_uint4(h2[0],  h2[1],  h2[2],  h2[3]);
        d[1] = make_uint4(h2[4],  h2[5],  h2[6],  h2[7]);
        d[2] = make_uint4(h2[8],  h2[9],  h2[10], h2[11]);
        d[3] = make_uint4(h2[12], h2[13], h2[14], h2[15]);
    } else {
        const int idx = tid - 128;
        const int n = 32 + (idx >> 1);
        const int mh = idx & 1;
        const float bn = cb[n];
        const float* gfc_n = &g_gfc[(b*96 + n)*4];
        float sum = 0.0f;
        #pragma unroll 8
        for (int mi = 0; mi < 64; mi++) {
            int m = mh*64 + mi;
            int y = y0 + (m >> 5), x = x0 + (m & 31);
            int v = ((y == 0) ? 2 : 0) | ((x == 0) ? 1 : 0);
            sum += tanhf(gates1[(size_t)n*GSTR2 + m] + bn + gfc_n[v]);
        }
        atomicAdd(&g_gfsum[b*GFC + (n - 32)], sum);
    }
}

// ---------------------------------------------------------------------------
// conv2 implicit GEMM fp16 (R8 layout, 3-stage pipeline) + fused LSTM epilogue
// Grid (160, NB), 256 thr. 4th kernel launch -> ncu-profiled.
// ---------------------------------------------------------------------------
__device__ __forceinline__ void load_slice(int s, uint32_t base,
                                           const __half* xin_b, int y0, int x0, int tid) {
    const int tap = s >> 1, h = s & 1;
    const int ky = tap / 3, kx = tap - ky*3;
    #pragma unroll
    for (int i = 0; i < 2; i++) {
        int cid = tid + 256*i;          // < 512
        int r = cid >> 2, c = cid & 3;
        const __half* src = xin_b
            + ((size_t)(y0 + (r >> 5) + ky) * XCOLS + (x0 + (r & 31) + kx)) * 64
            + h*32 + c*8;
        cp16(base + (uint32_t)(r*(C2STR*2) + c*16), src);
    }
    const __half* gw = g_wre + (size_t)s * 4096;
    #pragma unroll
    for (int i = 0; i < 2; i++) {
        int cid = tid + 256*i;
        int r = cid >> 2, c = cid & 3;
        cp16(base + 10240u + (uint32_t)(r*(C2STR*2) + c*16), gw + r*32 + c*8);
    }
}

__global__ __launch_bounds__(256) void conv2_mma(
    const float* __restrict__ prev_c, const float* __restrict__ gb,
    float* __restrict__ out)
{
    extern __shared__ __align__(16) float smem[];
    __half* hb = (__half*)smem;
    float* gates_s = smem;
    __shared__ float bias_s[128];

    const uint32_t su = smem_u32(smem);
    const int tid = threadIdx.x;
    const int lane = tid & 31, wid = tid >> 5;
    const int warp_m = wid & 3, warp_n = wid >> 2;
    const int tile = blockIdx.x, b = blockIdx.y;
    const int y0 = (tile / 5) * 4, x0 = (tile % 5) * 32;

    if (tid < 128) bias_s[tid] = gb[tid];

    const __half* xin_b = g_xin + (size_t)b * XROWS * XCOLS * 64;

    float acc[2][8][4] = {};

    // 3-stage prologue
    load_slice(0, su,                xin_b, y0, x0, tid); CP_COMMIT();
    load_slice(1, su + SLICEBUF_B,   xin_b, y0, x0, tid); CP_COMMIT();
    load_slice(2, su + 2*SLICEBUF_B, xin_b, y0, x0, tid); CP_COMMIT();

    const int qr = lane >> 2, qc = lane & 3;

    for (int s = 0; s < 18; s++) {
        const uint32_t base = (uint32_t)((s % 3) * SLICEBUF_B);
        CP_WAIT2();
        __syncthreads();

        const __half* Ah = hb + base/2 + warp_m*32*C2STR;
        const __half* Bh = hb + base/2 + 5120 + warp_n*64*C2STR;

        #pragma unroll
        for (int kc = 0; kc < 2; kc++) {
            uint32_t af[2][4], bf[8][2];
            #pragma unroll
            for (int mt = 0; mt < 2; mt++) {
                const __half* ap = Ah + (mt*16 + qr)*C2STR + kc*16 + 2*qc;
                af[mt][0] = ldh2(ap);
                af[mt][1] = ldh2(ap + 8*C2STR);
                af[mt][2] = ldh2(ap + 8);
                af[mt][3] = ldh2(ap + 8*C2STR + 8);
            }
            #pragma unroll
            for (int nt = 0; nt < 8; nt++) {
                const __half* bp = Bh + (nt*8 + qr)*C2STR + kc*16 + 2*qc;
                bf[nt][0] = ldh2(bp);
                bf[nt][1] = ldh2(bp + 8);
            }
            #pragma unroll
            for (int mt = 0; mt < 2; mt++)
                #pragma unroll
                for (int nt = 0; nt < 8; nt++)
                    mma16816(acc[mt][nt], af[mt], bf[nt]);
        }

        __syncthreads();
        if (s + 3 < 18)
            load_slice(s + 3, su + base, xin_b, y0, x0, tid);
        CP_COMMIT();
    }

    // ---- epilogue: accums -> smem [n][m], fused LSTM ----
    __syncthreads();
    #pragma unroll
    for (int mt = 0; mt < 2; mt++) {
        int m = warp_m*32 + mt*16 + qr;
        #pragma unroll
        for (int nt = 0; nt < 8; nt++) {
            int n = warp_n*64 + nt*8 + 2*qc;
            gates_s[(size_t)n*GSTR2 + m]         = acc[mt][nt][0];
            gates_s[(size_t)(n+1)*GSTR2 + m]     = acc[mt][nt][1];
            gates_s[(size_t)n*GSTR2 + m + 8]     = acc[mt][nt][2];
            gates_s[(size_t)(n+1)*GSTR2 + m + 8] = acc[mt][nt][3];
        }
    }
    __syncthreads();

    if (tid < 128) {
        const int m = tid;
        const int y = y0 + (m >> 5), x = x0 + (m & 31);
        #pragma unroll
        for (int j = 0; j < 32; j++) {
            float ig = gates_s[(size_t)(j     )*GSTR2 + m] + bias_s[j];
            float rg = gates_s[(size_t)(j + 32)*GSTR2 + m] + bias_s[32 + j];
            float og = gates_s[(size_t)(j + 64)*GSTR2 + m] + bias_s[64 + j];
            float cg = gates_s[(size_t)(j + 96)*GSTR2 + m] + bias_s[96 + j];
            size_t hc = (((size_t)b*OUT_CH + j)*HFULL2 + y)*WFULL2 + EX2 + x;
            float pc = prev_c[hc];
            float cell = sigf(rg)*pc + sigf(ig)*tanhf(cg);
            float hid  = sigf(og)*tanhf(cell);
            out[(((size_t)b*OUT_CH + j)*OH + y)*OW + x] = hid;
            out[OFF_H + hc] = hid;
            out[OFF_C + hc] = cell;
        }
    }
}

// ---------------------------------------------------------------------------
// new_gf
// ---------------------------------------------------------------------------
__global__ void gf_kernel(const float* __restrict__ gf, float* __restrict__ out) {
    int i = threadIdx.x;
    out[OFF_GF + i] = tanhf(gf[i] + g_gfsum[i] * (1.0f / (float)(OH*OW)));
}

// ---------------------------------------------------------------------------
// copy prev_h/prev_c -> out, skipping the interior region conv2 overwrites
// ---------------------------------------------------------------------------
__global__ void copy_hc(const float* __restrict__ ph, const float* __restrict__ pc,
                        float* __restrict__ out) {
    const int row = blockIdx.x;
    const int plane = blockIdx.y;
    const int t = threadIdx.x;
    if (t >= 80) return;
    if (row < 128 && t >= 16 && t < 56) return;
    size_t off = ((size_t)plane*HFULL2 + row)*WFULL2 + t*4;
    float4 vh = *(const float4*)(ph + off);
    float4 vc = *(const float4*)(pc + off);
    *(float4*)(out + OFF_H + off) = vh;
    *(float4*)(out + OFF_C + off) = vc;
}

// ---------------------------------------------------------------------------
// Launch: prep_all(1), transforms(2), conv1(3), conv2(4 <- profiled), gf, copy
// ---------------------------------------------------------------------------
extern "C" void kernel_launch(void* const* d_in, const int* in_sizes, int n_in,
                              void* d_out, int out_size) {
    const float* x       = (const float*)d_in[0];
    const float* prev_h  = (const float*)d_in[1];
    const float* prev_c  = (const float*)d_in[2];
    const float* gf      = (const float*)d_in[3];
    const float* conv_w  = (const float*)d_in[4];
    const float* conv_b  = (const float*)d_in[5];
    const float* gates_w = (const float*)d_in[6];
    const float* gates_b = (const float*)d_in[7];
    float* out = (float*)d_out;

    const int stage2 = 3 * SLICEBUF_B;                            // 61440
    const int gates2 = 128 * GSTR2 * (int)sizeof(float);          // 66048
    const int smem2 = stage2 > gates2 ? stage2 : gates2;          // 66048
    const int smem1 = 96 * GSTR2 * (int)sizeof(float);            // 49536
    cudaFuncSetAttribute(conv2_mma, cudaFuncAttributeMaxDynamicSharedMemorySize, smem2);
    cudaFuncSetAttribute(conv1_mma, cudaFuncAttributeMaxDynamicSharedMemorySize, smem1);

    prep_all<<<dim3(288, 4), 256>>>(gf, conv_w, gates_w);
    transforms<<<dim3(256, NB, 2), 320>>>(x, prev_h);
    conv1_mma<<<dim3(160, NB), 256, smem1>>>(conv_b);
    conv2_mma<<<dim3(160, NB), 256, smem2>>>(prev_c, gates_b, out);
    gf_kernel<<<1, NB*GFC>>>(gf, out);
    copy_hc<<<dim3(HFULL2, NB*OUT_CH), 128>>>(prev_h, prev_c, out);
}

// round 11
// speedup vs baseline: 1.3893x; 1.1344x over previous
#include <cuda_runtime.h>
#include <cuda_fp16.h>
#include <cstdint>
#include <cstddef>

// ---------------------------------------------------------------------------
// Problem constants
// ---------------------------------------------------------------------------
#define NB     8
#define IN_CH  16
#define OUT_CH 32
#define GFC    64
#define EH     256
#define EW     320
#define OH     128
#define OW     160
#define EX2    64
#define HFULL2 256
#define WFULL2 320
#define XROWS  130
#define XCOLS  162
#define X1R    258
#define X1C    322

#define N_HID  ((size_t)NB*OUT_CH*OH*OW)
#define N_HC   ((size_t)NB*OUT_CH*HFULL2*WFULL2)
#define OFF_H  (N_HID)
#define OFF_C  (N_HID + N_HC)
#define OFF_GF (N_HID + 2*N_HC)

// conv2 staging (halves): per-slice = A(64px x 40) + B(128oc x 40)
#define C2STR   40
#define SLICE2B 15360             // bytes: 5120 A + 10240 B
#define GM2     65                // conv2 epilogue gates stride (floats)
// conv1 staging (halves)
#define C1STR    24
#define A1SLICE (128*C1STR)
#define B1SLICE (96*C1STR)
#define GSTR2 129

// ---------------------------------------------------------------------------
// Scratch
// ---------------------------------------------------------------------------
__device__ __half g_xin[NB*XROWS*XCOLS*64];   // NHWC conv2 input
__device__ __half g_x1[NB*X1R*X1C*16];        // NHWC conv1 input
__device__ __half g_wre[18*128*32];           // conv2 w [slice][oc][32ic]
__device__ __half g_w1[9*96*16];              // conv1 w [tap][oc][16ic]
__device__ float  g_gfsum[NB*GFC];
__device__ float  g_gfc[NB*96*4];

__device__ __forceinline__ float sigf(float x) { return 1.0f / (1.0f + expf(-x)); }

__device__ __forceinline__ uint32_t pack_h2(float a, float b) {
    __half2 h = __floats2half2_rn(a, b);
    return *reinterpret_cast<uint32_t*>(&h);
}
__device__ __forceinline__ uint32_t ldh2(const __half* p) {
    return *(const uint32_t*)p;
}
__device__ __forceinline__ uint32_t smem_u32(const void* p) {
    uint32_t a;
    asm("{ .reg .u64 t; cvta.to.shared.u64 t, %1; cvt.u32.u64 %0, t; }"
        : "=r"(a) : "l"(p));
    return a;
}
__device__ __forceinline__ void cp16(uint32_t dst, const void* src) {
    asm volatile("cp.async.cg.shared.global [%0], [%1], 16;"
                 :: "r"(dst), "l"(src) : "memory");
}
#define CP_COMMIT() asm volatile("cp.async.commit_group;" ::: "memory")
#define CP_WAIT1()  asm volatile("cp.async.wait_group 1;" ::: "memory")
#define CP_WAIT3()  asm volatile("cp.async.wait_group 3;" ::: "memory")

// mma m16n8k16 fp16 -> fp32 accumulate
__device__ __forceinline__ void mma16816(float* c, const uint32_t* a, const uint32_t* b) {
    asm volatile(
        "mma.sync.aligned.m16n8k16.row.col.f32.f16.f16.f32 "
        "{%0,%1,%2,%3}, {%4,%5,%6,%7}, {%8,%9}, {%0,%1,%2,%3};"
        : "+f"(c[0]), "+f"(c[1]), "+f"(c[2]), "+f"(c[3])
        : "r"(a[0]), "r"(a[1]), "r"(a[2]), "r"(a[3]), "r"(b[0]), "r"(b[1]));
}

// ---------------------------------------------------------------------------
// prep_all: role by blockIdx.y
// ---------------------------------------------------------------------------
__global__ void prep_all(const float* __restrict__ gf, const float* __restrict__ w,
                         const float* __restrict__ gw) {
    const int role = blockIdx.y;
    const int idx = blockIdx.x * 256 + threadIdx.x;
    if (role == 0) {
        if (idx < NB*GFC) g_gfsum[idx] = 0.0f;
        if (idx >= NB*96*4) return;
        int v  = idx & 3;
        int oc = (idx >> 2) % 96;
        int b  = idx / (96*4);
        int ky0 = (v >> 1) & 1, kx0 = v & 1;
        float s = 0.0f;
        for (int c = 0; c < GFC; c++) {
            const float* wp = w + ((size_t)(oc*80) + IN_CH + c) * 9;
            float wsum = 0.0f;
            for (int ky = ky0; ky < 3; ky++)
                for (int kx = kx0; kx < 3; kx++)
                    wsum += wp[ky*3 + kx];
            s += gf[b*GFC + c] * wsum;
        }
        g_gfc[idx] = s;
    } else if (role == 1) {
        if (idx >= 18*128*32) return;
        int icl = idx & 31;
        int oc  = (idx >> 5) & 127;
        int s   = idx >> 12;
        int tap = s >> 1, h = s & 1;
        g_wre[idx] = __float2half_rn(gw[((size_t)oc*64 + h*32 + icl)*9 + tap]);
    } else if (role == 2) {
        if (idx >= 9*96*16) return;
        int ic  = idx & 15;
        int oc  = (idx >> 4) % 96;
        int tap = idx / (96*16);
        g_w1[idx] = __float2half_rn(w[((size_t)oc*80 + ic)*9 + tap]);
    } else {
        if (idx >= NB * 580) return;
        int pos = idx % 580;
        int b = idx / 580;
        int row, col;
        if      (pos < 162) { row = 0;   col = pos; }
        else if (pos < 324) { row = 129; col = pos - 162; }
        else if (pos < 452) { row = pos - 324 + 1; col = 0; }
        else                { row = pos - 452 + 1; col = 161; }
        uint4* p = (uint4*)&g_xin[(((size_t)b*XROWS + row)*XCOLS + col)*64];
        uint4 z = {0,0,0,0};
        p[0] = z; p[1] = z; p[2] = z; p[3] = z;
    }
}

// ---------------------------------------------------------------------------
// transforms: role by blockIdx.z (0: x->g_x1, 1: prev_h->g_xin ch32..63)
// ---------------------------------------------------------------------------
__global__ void transforms(const float* __restrict__ x, const float* __restrict__ prev_h) {
    __shared__ float sm[32*163];
    const int b = blockIdx.y;
    const int t = threadIdx.x;
    if (blockIdx.z == 0) {
        const int gy = blockIdx.x;
        for (int i = t; i < 16*80; i += 320) {
            int ic = i / 80, g4 = (i % 80) * 4;
            float4 v = *(const float4*)&x[(((size_t)b*16 + ic)*EH + gy)*EW + g4];
            float* s = &sm[ic*321 + g4];
            s[0] = v.x; s[1] = v.y; s[2] = v.z; s[3] = v.w;
        }
        __syncthreads();
        __half* rowp = g_x1 + ((size_t)b*X1R + gy + 1)*X1C*16;
        {
            const int gx = t;
            uint32_t h2[8];
            #pragma unroll
            for (int j = 0; j < 8; j++)
                h2[j] = pack_h2(sm[(2*j)*321 + gx], sm[(2*j+1)*321 + gx]);
            uint4* d = (uint4*)(rowp + (size_t)(gx + 1)*16);
            d[0] = make_uint4(h2[0], h2[1], h2[2], h2[3]);
            d[1] = make_uint4(h2[4], h2[5], h2[6], h2[7]);
        }
        if (t == 0) {
            uint4* d = (uint4*)rowp;
            uint4 z = {0,0,0,0};
            d[0] = z; d[1] = z;
        }
        if (gy == 0) {
            uint4* r0 = (uint4*)(g_x1 + (size_t)b*X1R*X1C*16);
            uint4 z = {0,0,0,0};
            for (int i = t; i < X1C*16/8; i += 320) r0[i] = z;
        }
    } else {
        const int row = blockIdx.x;
        if (row >= XROWS) return;
        if (row == 0) {
            if (t < 162) {
                uint4* d = (uint4*)&g_xin[(((size_t)b*XROWS)*XCOLS + t)*64 + 32];
                uint4 z = {0,0,0,0};
                d[0] = z; d[1] = z; d[2] = z; d[3] = z;
            }
            return;
        }
        for (int i = t; i < 32*162; i += 320) {
            int ic = i / 162, col = i % 162;
            sm[ic*163 + col] = prev_h[(((size_t)b*OUT_CH + ic)*HFULL2 + row - 1)*WFULL2 + 63 + col];
        }
        __syncthreads();
        if (t < 162) {
            const int col = t;
            uint32_t h2[16];
            #pragma unroll
            for (int j = 0; j < 16; j++)
                h2[j] = pack_h2(sm[(2*j)*163 + col], sm[(2*j+1)*163 + col]);
            uint4* d = (uint4*)&g_xin[(((size_t)b*XROWS + row)*XCOLS + col)*64 + 32];
            d[0] = make_uint4(h2[0],  h2[1],  h2[2],  h2[3]);
            d[1] = make_uint4(h2[4],  h2[5],  h2[6],  h2[7]);
            d[2] = make_uint4(h2[8],  h2[9],  h2[10], h2[11]);
            d[3] = make_uint4(h2[12], h2[13], h2[14], h2[15]);
        }
    }
}

// ---------------------------------------------------------------------------
// conv1 implicit GEMM fp16 (R8-proven): M=128, N=96, K=144
// ---------------------------------------------------------------------------
__device__ __forceinline__ void load_slice1(int s, uint32_t ab, uint32_t bb,
                                            const __half* x1_b, int y0, int x0, int tid) {
    const int ky = s / 3, kx = s - 3*ky;
    {
        int r = tid >> 1, c = tid & 1;
        int y = y0 + (r >> 5), x = x0 + (r & 31);
        const __half* src = x1_b + ((size_t)(2*y + ky)*X1C + (2*x + kx))*16 + c*8;
        cp16(ab + (uint32_t)(r*(C1STR*2) + c*16), src);
    }
    if (tid < 192) {
        int r = tid >> 1, c = tid & 1;
        const __half* src = g_w1 + (size_t)s*1536 + r*16 + c*8;
        cp16(bb + (uint32_t)(r*(C1STR*2) + c*16), src);
    }
}

__global__ __launch_bounds__(256) void conv1_mma(const float* __restrict__ cb) {
    extern __shared__ __align__(16) float smem[];
    __half* hb = (__half*)smem;
    float* gates1 = smem;

    const uint32_t su = smem_u32(smem);
    const int tid = threadIdx.x;
    const int lane = tid & 31, wid = tid >> 5;
    const int warp_m = wid & 3, warp_n = wid >> 2;
    const int tile = blockIdx.x, b = blockIdx.y;
    const int y0 = (tile / 5) * 4, x0 = (tile % 5) * 32;

    const __half* x1_b = g_x1 + (size_t)b * X1R * X1C * 16;

    float acc[2][6][4] = {};

    load_slice1(0, su,        su + 12288, x1_b, y0, x0, tid); CP_COMMIT();
    load_slice1(1, su + 6144, su + 16896, x1_b, y0, x0, tid); CP_COMMIT();

    const int qr = lane >> 2, qc = lane & 3;

    for (int s = 0; s < 9; s++) {
        const int buf = s & 1;
        CP_WAIT1();
        __syncthreads();

        const __half* Ah = hb + buf*A1SLICE + warp_m*32*C1STR;
        const __half* Bh = hb + 2*A1SLICE + buf*B1SLICE + warp_n*48*C1STR;

        uint32_t af[2][4], bf[6][2];
        #pragma unroll
        for (int mt = 0; mt < 2; mt++) {
            const __half* ap = Ah + (mt*16 + qr)*C1STR + 2*qc;
            af[mt][0] = ldh2(ap);
            af[mt][1] = ldh2(ap + 8*C1STR);
            af[mt][2] = ldh2(ap + 8);
            af[mt][3] = ldh2(ap + 8*C1STR + 8);
        }
        #pragma unroll
        for (int nt = 0; nt < 6; nt++) {
            const __half* bp = Bh + (nt*8 + qr)*C1STR + 2*qc;
            bf[nt][0] = ldh2(bp);
            bf[nt][1] = ldh2(bp + 8);
        }
        #pragma unroll
        for (int mt = 0; mt < 2; mt++)
            #pragma unroll
            for (int nt = 0; nt < 6; nt++)
                mma16816(acc[mt][nt], af[mt], bf[nt]);

        __syncthreads();
        if (s + 2 < 9)
            load_slice1(s + 2, su + buf*6144, su + 12288 + buf*4608,
                        x1_b, y0, x0, tid);
        CP_COMMIT();
    }

    __syncthreads();
    #pragma unroll
    for (int mt = 0; mt < 2; mt++) {
        int m = warp_m*32 + mt*16 + qr;
        #pragma unroll
        for (int nt = 0; nt < 6; nt++) {
            int n = warp_n*48 + nt*8 + 2*qc;
            gates1[(size_t)n*GSTR2 + m]         = acc[mt][nt][0];
            gates1[(size_t)(n+1)*GSTR2 + m]     = acc[mt][nt][1];
            gates1[(size_t)n*GSTR2 + m + 8]     = acc[mt][nt][2];
            gates1[(size_t)(n+1)*GSTR2 + m + 8] = acc[mt][nt][3];
        }
    }
    __syncthreads();

    if (tid < 128) {
        const int m = tid;
        const int y = y0 + (m >> 5), x = x0 + (m & 31);
        const int v = ((y == 0) ? 2 : 0) | ((x == 0) ? 1 : 0);
        float vals[32];
        #pragma unroll
        for (int n = 0; n < 32; n++)
            vals[n] = tanhf(gates1[(size_t)n*GSTR2 + m] + cb[n]
                            + g_gfc[(b*96 + n)*4 + v]);
        uint32_t h2[16];
        #pragma unroll
        for (int j = 0; j < 16; j++) h2[j] = pack_h2(vals[2*j], vals[2*j+1]);
        uint4* d = (uint4*)&g_xin[(((size_t)b*XROWS + y + 1)*XCOLS + x + 1)*64];
        d[0] = make_uint4(h2[0],  h2[1],  h2[2],  h2[3]);
        d[1] = make_uint4(h2[4],  h2[5],  h2[6],  h2[7]);
        d[2] = make_uint4(h2[8],  h2[9],  h2[10], h2[11]);
        d[3] = make_uint4(h2[12], h2[13], h2[14], h2[15]);
    } else {
        const int idx = tid - 128;
        const int n = 32 + (idx >> 1);
        const int mh = idx & 1;
        const float bn = cb[n];
        const float* gfc_n = &g_gfc[(b*96 + n)*4];
        float sum = 0.0f;
        #pragma unroll 8
        for (int mi = 0; mi < 64; mi++) {
            int m = mh*64 + mi;
            int y = y0 + (m >> 5), x = x0 + (m & 31);
            int v = ((y == 0) ? 2 : 0) | ((x == 0) ? 1 : 0);
            sum += tanhf(gates1[(size_t)n*GSTR2 + m] + bn + gfc_n[v]);
        }
        atomicAdd(&g_gfsum[b*GFC + (n - 32)], sum);
    }
}

// ---------------------------------------------------------------------------
// conv2 implicit GEMM fp16: 64px x 128oc per CTA, 4-stage pipeline,
// fused LSTM epilogue. Grid (320, NB), 256 thr, 3 CTAs/SM target.
// ---------------------------------------------------------------------------
__device__ __forceinline__ void load_slice(int s, uint32_t base,
                                           const __half* xin_b, int y0, int x0, int tid) {
    const int tap = s >> 1, h = s & 1;
    const int ky = tap / 3, kx = tap - ky*3;
    {   // A: 64 px x 4 chunks = 256 cp16
        int r = tid >> 2, c = tid & 3;
        const __half* src = xin_b
            + ((size_t)(y0 + (r >> 5) + ky) * XCOLS + (x0 + (r & 31) + kx)) * 64
            + h*32 + c*8;
        cp16(base + (uint32_t)(r*(C2STR*2) + c*16), src);
    }
    const __half* gw = g_wre + (size_t)s * 4096;
    #pragma unroll
    for (int i = 0; i < 2; i++) {   // B: 128 oc x 4 chunks = 512 cp16
        int cid = tid + 256*i;
        int r = cid >> 2, c = cid & 3;
        cp16(base + 5120u + (uint32_t)(r*(C2STR*2) + c*16), gw + r*32 + c*8);
    }
}

__global__ __launch_bounds__(256, 3) void conv2_mma(
    const float* __restrict__ prev_c, const float* __restrict__ gb,
    float* __restrict__ out)
{
    extern __shared__ __align__(16) float smem[];
    __half* hb = (__half*)smem;
    float* gates_s = smem;
    __shared__ float bias_s[128];

    const uint32_t su = smem_u32(smem);
    const int tid = threadIdx.x;
    const int lane = tid & 31, wid = tid >> 5;
    const int warp_m = wid & 1, warp_n = wid >> 1;
    const int tile = blockIdx.x, b = blockIdx.y;
    const int y0 = (tile / 5) * 2, x0 = (tile % 5) * 32;

    if (tid < 128) bias_s[tid] = gb[tid];

    const __half* xin_b = g_xin + (size_t)b * XROWS * XCOLS * 64;

    float acc[2][4][4] = {};

    // 4-stage prologue
    load_slice(0, su,             xin_b, y0, x0, tid); CP_COMMIT();
    load_slice(1, su +   SLICE2B, xin_b, y0, x0, tid); CP_COMMIT();
    load_slice(2, su + 2*SLICE2B, xin_b, y0, x0, tid); CP_COMMIT();
    load_slice(3, su + 3*SLICE2B, xin_b, y0, x0, tid); CP_COMMIT();

    const int qr = lane >> 2, qc = lane & 3;

    for (int s = 0; s < 18; s++) {
        const uint32_t base = (uint32_t)((s & 3) * SLICE2B);
        CP_WAIT3();
        __syncthreads();

        const __half* Ah = hb + base/2 + warp_m*32*C2STR;
        const __half* Bh = hb + base/2 + 2560 + warp_n*32*C2STR;

        #pragma unroll
        for (int kc = 0; kc < 2; kc++) {
            uint32_t af[2][4], bf[4][2];
            #pragma unroll
            for (int mt = 0; mt < 2; mt++) {
                const __half* ap = Ah + (mt*16 + qr)*C2STR + kc*16 + 2*qc;
                af[mt][0] = ldh2(ap);
                af[mt][1] = ldh2(ap + 8*C2STR);
                af[mt][2] = ldh2(ap + 8);
                af[mt][3] = ldh2(ap + 8*C2STR + 8);
            }
            #pragma unroll
            for (int nt = 0; nt < 4; nt++) {
                const __half* bp = Bh + (nt*8 + qr)*C2STR + kc*16 + 2*qc;
                bf[nt][0] = ldh2(bp);
                bf[nt][1] = ldh2(bp + 8);
            }
            #pragma unroll
            for (int mt = 0; mt < 2; mt++)
                #pragma unroll
                for (int nt = 0; nt < 4; nt++)
                    mma16816(acc[mt][nt], af[mt], bf[nt]);
        }

        __syncthreads();
        if (s + 4 < 18)
            load_slice(s + 4, su + base, xin_b, y0, x0, tid);
        CP_COMMIT();
    }

    // ---- epilogue: accums -> smem [n][m] (m=64 px), fused LSTM ----
    __syncthreads();
    #pragma unroll
    for (int mt = 0; mt < 2; mt++) {
        int m = warp_m*32 + mt*16 + qr;
        #pragma unroll
        for (int nt = 0; nt < 4; nt++) {
            int n = warp_n*32 + nt*8 + 2*qc;
            gates_s[(size_t)n*GM2 + m]         = acc[mt][nt][0];
            gates_s[(size_t)(n+1)*GM2 + m]     = acc[mt][nt][1];
            gates_s[(size_t)n*GM2 + m + 8]     = acc[mt][nt][2];
            gates_s[(size_t)(n+1)*GM2 + m + 8] = acc[mt][nt][3];
        }
    }
    __syncthreads();

    {   // 256 threads: px = tid>>2 (0..63), 8 oc each
        const int m = tid >> 2;
        const int j0 = (tid & 3) * 8;
        const int y = y0 + (m >> 5), x = x0 + (m & 31);
        #pragma unroll
        for (int i = 0; i < 8; i++) {
            const int j = j0 + i;
            float ig = gates_s[(size_t)(j     )*GM2 + m] + bias_s[j];
            float rg = gates_s[(size_t)(j + 32)*GM2 + m] + bias_s[32 + j];
            float og = gates_s[(size_t)(j + 64)*GM2 + m] + bias_s[64 + j];
            float cg = gates_s[(size_t)(j + 96)*GM2 + m] + bias_s[96 + j];
            size_t hc = (((size_t)b*OUT_CH + j)*HFULL2 + y)*WFULL2 + EX2 + x;
            float pc = prev_c[hc];
            float cell = sigf(rg)*pc + sigf(ig)*tanhf(cg);
            float hid  = sigf(og)*tanhf(cell);
            out[(((size_t)b*OUT_CH + j)*OH + y)*OW + x] = hid;
            out[OFF_H + hc] = hid;
            out[OFF_C + hc] = cell;
        }
    }
}

// ---------------------------------------------------------------------------
// new_gf
// ---------------------------------------------------------------------------
__global__ void gf_kernel(const float* __restrict__ gf, float* __restrict__ out) {
    int i = threadIdx.x;
    out[OFF_GF + i] = tanhf(gf[i] + g_gfsum[i] * (1.0f / (float)(OH*OW)));
}

// ---------------------------------------------------------------------------
// copy prev_h/prev_c -> out, skipping the interior region conv2 overwrites
// ---------------------------------------------------------------------------
__global__ void copy_hc(const float* __restrict__ ph, const float* __restrict__ pc,
                        float* __restrict__ out) {
    const int row = blockIdx.x;
    const int plane = blockIdx.y;
    const int t = threadIdx.x;
    if (t >= 80) return;
    if (row < 128 && t >= 16 && t < 56) return;
    size_t off = ((size_t)plane*HFULL2 + row)*WFULL2 + t*4;
    float4 vh = *(const float4*)(ph + off);
    float4 vc = *(const float4*)(pc + off);
    *(float4*)(out + OFF_H + off) = vh;
    *(float4*)(out + OFF_C + off) = vc;
}

// ---------------------------------------------------------------------------
// Launch: prep_all(1), transforms(2), conv1(3), conv2(4 <- profiled), gf, copy
// ---------------------------------------------------------------------------
extern "C" void kernel_launch(void* const* d_in, const int* in_sizes, int n_in,
                              void* d_out, int out_size) {
    const float* x       = (const float*)d_in[0];
    const float* prev_h  = (const float*)d_in[1];
    const float* prev_c  = (const float*)d_in[2];
    const float* gf      = (const float*)d_in[3];
    const float* conv_w  = (const float*)d_in[4];
    const float* conv_b  = (const float*)d_in[5];
    const float* gates_w = (const float*)d_in[6];
    const float* gates_b = (const float*)d_in[7];
    float* out = (float*)d_out;

    const int stage2 = 4 * SLICE2B;                               // 61440
    const int gates2 = 128 * GM2 * (int)sizeof(float);            // 33280
    const int smem2 = stage2 > gates2 ? stage2 : gates2;          // 61440
    const int smem1 = 96 * GSTR2 * (int)sizeof(float);            // 49536
    cudaFuncSetAttribute(conv2_mma, cudaFuncAttributeMaxDynamicSharedMemorySize, smem2);
    cudaFuncSetAttribute(conv1_mma, cudaFuncAttributeMaxDynamicSharedMemorySize, smem1);

    prep_all<<<dim3(288, 4), 256>>>(gf, conv_w, gates_w);
    transforms<<<dim3(256, NB, 2), 320>>>(x, prev_h);
    conv1_mma<<<dim3(160, NB), 256, smem1>>>(conv_b);
    conv2_mma<<<dim3(320, NB), 256, smem2>>>(prev_c, gates_b, out);
    gf_kernel<<<1, NB*GFC>>>(gf, out);
    copy_hc<<<dim3(HFULL2, NB*OUT_CH), 128>>>(prev_h, prev_c, out);
}

// round 12
// speedup vs baseline: 1.4565x; 1.0483x over previous
#include <cuda_runtime.h>
#include <cuda_fp16.h>
#include <cstdint>
#include <cstddef>

// ---------------------------------------------------------------------------
// Problem constants
// ---------------------------------------------------------------------------
#define NB     8
#define IN_CH  16
#define OUT_CH 32
#define GFC    64
#define EH     256
#define EW     320
#define OH     128
#define OW     160
#define EX2    64
#define HFULL2 256
#define WFULL2 320
#define XROWS  130
#define XCOLS  162
#define X1R    258
#define X1C    322

#define N_HID  ((size_t)NB*OUT_CH*OH*OW)
#define N_HC   ((size_t)NB*OUT_CH*HFULL2*WFULL2)
#define OFF_H  (N_HID)
#define OFF_C  (N_HID + N_HC)
#define OFF_GF (N_HID + 2*N_HC)

// conv2 staging (halves): per-slice = A(64px x 40) + B(128oc x 40)
#define C2STR   40
#define SLICE2B 15360             // bytes: 5120 A + 10240 B
#define GM2     65                // conv2 epilogue gates stride (floats)
// conv1 staging (halves)
#define C1STR    24
#define A1SLICE (128*C1STR)
#define B1SLICE (96*C1STR)
#define GSTR2 129

// ---------------------------------------------------------------------------
// Scratch
// ---------------------------------------------------------------------------
__device__ __half g_xin[NB*XROWS*XCOLS*64];   // NHWC conv2 input
__device__ __half g_x1[NB*X1R*X1C*16];        // NHWC conv1 input
__device__ __half g_wre[18*128*32];           // conv2 w [slice][oc][32ic]
__device__ __half g_w1[9*96*16];              // conv1 w [tap][oc][16ic]
__device__ float  g_gfsum[NB*GFC];
__device__ float  g_gfc[NB*96*4];

__device__ __forceinline__ float sigf(float x) { return 1.0f / (1.0f + expf(-x)); }

__device__ __forceinline__ uint32_t pack_h2(float a, float b) {
    __half2 h = __floats2half2_rn(a, b);
    return *reinterpret_cast<uint32_t*>(&h);
}
__device__ __forceinline__ uint32_t ldh2(const __half* p) {
    return *(const uint32_t*)p;
}
__device__ __forceinline__ uint32_t smem_u32(const void* p) {
    uint32_t a;
    asm("{ .reg .u64 t; cvta.to.shared.u64 t, %1; cvt.u32.u64 %0, t; }"
        : "=r"(a) : "l"(p));
    return a;
}
__device__ __forceinline__ void cp16(uint32_t dst, const void* src) {
    asm volatile("cp.async.cg.shared.global [%0], [%1], 16;"
                 :: "r"(dst), "l"(src) : "memory");
}
#define CP_COMMIT() asm volatile("cp.async.commit_group;" ::: "memory")
#define CP_WAIT1()  asm volatile("cp.async.wait_group 1;" ::: "memory")
#define CP_WAIT3()  asm volatile("cp.async.wait_group 3;" ::: "memory")

// ldmatrix x4 (fragment loads)
#define LDSM4(arr, addr) \
    asm volatile("ldmatrix.sync.aligned.m8n8.x4.shared.b16 {%0,%1,%2,%3}, [%4];" \
        : "=r"((arr)[0]), "=r"((arr)[1]), "=r"((arr)[2]), "=r"((arr)[3]) \
        : "r"(addr))

// mma m16n8k16 fp16 -> fp32 accumulate
__device__ __forceinline__ void mma16816(float* c, const uint32_t* a, const uint32_t* b) {
    asm volatile(
        "mma.sync.aligned.m16n8k16.row.col.f32.f16.f16.f32 "
        "{%0,%1,%2,%3}, {%4,%5,%6,%7}, {%8,%9}, {%0,%1,%2,%3};"
        : "+f"(c[0]), "+f"(c[1]), "+f"(c[2]), "+f"(c[3])
        : "r"(a[0]), "r"(a[1]), "r"(a[2]), "r"(a[3]), "r"(b[0]), "r"(b[1]));
}

// ---------------------------------------------------------------------------
// prep_all: role by blockIdx.y
// ---------------------------------------------------------------------------
__global__ void prep_all(const float* __restrict__ gf, const float* __restrict__ w,
                         const float* __restrict__ gw) {
    const int role = blockIdx.y;
    const int idx = blockIdx.x * 256 + threadIdx.x;
    if (role == 0) {
        if (idx < NB*GFC) g_gfsum[idx] = 0.0f;
        if (idx >= NB*96*4) return;
        int v  = idx & 3;
        int oc = (idx >> 2) % 96;
        int b  = idx / (96*4);
        int ky0 = (v >> 1) & 1, kx0 = v & 1;
        float s = 0.0f;
        for (int c = 0; c < GFC; c++) {
            const float* wp = w + ((size_t)(oc*80) + IN_CH + c) * 9;
            float wsum = 0.0f;
            for (int ky = ky0; ky < 3; ky++)
                for (int kx = kx0; kx < 3; kx++)
                    wsum += wp[ky*3 + kx];
            s += gf[b*GFC + c] * wsum;
        }
        g_gfc[idx] = s;
    } else if (role == 1) {
        if (idx >= 18*128*32) return;
        int icl = idx & 31;
        int oc  = (idx >> 5) & 127;
        int s   = idx >> 12;
        int tap = s >> 1, h = s & 1;
        g_wre[idx] = __float2half_rn(gw[((size_t)oc*64 + h*32 + icl)*9 + tap]);
    } else if (role == 2) {
        if (idx >= 9*96*16) return;
        int ic  = idx & 15;
        int oc  = (idx >> 4) % 96;
        int tap = idx / (96*16);
        g_w1[idx] = __float2half_rn(w[((size_t)oc*80 + ic)*9 + tap]);
    } else {
        if (idx >= NB * 580) return;
        int pos = idx % 580;
        int b = idx / 580;
        int row, col;
        if      (pos < 162) { row = 0;   col = pos; }
        else if (pos < 324) { row = 129; col = pos - 162; }
        else if (pos < 452) { row = pos - 324 + 1; col = 0; }
        else                { row = pos - 452 + 1; col = 161; }
        uint4* p = (uint4*)&g_xin[(((size_t)b*XROWS + row)*XCOLS + col)*64];
        uint4 z = {0,0,0,0};
        p[0] = z; p[1] = z; p[2] = z; p[3] = z;
    }
}

// ---------------------------------------------------------------------------
// transforms: role by blockIdx.z (0: x->g_x1, 1: prev_h->g_xin ch32..63)
// ---------------------------------------------------------------------------
__global__ void transforms(const float* __restrict__ x, const float* __restrict__ prev_h) {
    __shared__ float sm[32*163];
    const int b = blockIdx.y;
    const int t = threadIdx.x;
    if (blockIdx.z == 0) {
        const int gy = blockIdx.x;
        for (int i = t; i < 16*80; i += 320) {
            int ic = i / 80, g4 = (i % 80) * 4;
            float4 v = *(const float4*)&x[(((size_t)b*16 + ic)*EH + gy)*EW + g4];
            float* s = &sm[ic*321 + g4];
            s[0] = v.x; s[1] = v.y; s[2] = v.z; s[3] = v.w;
        }
        __syncthreads();
        __half* rowp = g_x1 + ((size_t)b*X1R + gy + 1)*X1C*16;
        {
            const int gx = t;
            uint32_t h2[8];
            #pragma unroll
            for (int j = 0; j < 8; j++)
                h2[j] = pack_h2(sm[(2*j)*321 + gx], sm[(2*j+1)*321 + gx]);
            uint4* d = (uint4*)(rowp + (size_t)(gx + 1)*16);
            d[0] = make_uint4(h2[0], h2[1], h2[2], h2[3]);
            d[1] = make_uint4(h2[4], h2[5], h2[6], h2[7]);
        }
        if (t == 0) {
            uint4* d = (uint4*)rowp;
            uint4 z = {0,0,0,0};
            d[0] = z; d[1] = z;
        }
        if (gy == 0) {
            uint4* r0 = (uint4*)(g_x1 + (size_t)b*X1R*X1C*16);
            uint4 z = {0,0,0,0};
            for (int i = t; i < X1C*16/8; i += 320) r0[i] = z;
        }
    } else {
        const int row = blockIdx.x;
        if (row >= XROWS) return;
        if (row == 0) {
            if (t < 162) {
                uint4* d = (uint4*)&g_xin[(((size_t)b*XROWS)*XCOLS + t)*64 + 32];
                uint4 z = {0,0,0,0};
                d[0] = z; d[1] = z; d[2] = z; d[3] = z;
            }
            return;
        }
        for (int i = t; i < 32*162; i += 320) {
            int ic = i / 162, col = i % 162;
            sm[ic*163 + col] = prev_h[(((size_t)b*OUT_CH + ic)*HFULL2 + row - 1)*WFULL2 + 63 + col];
        }
        __syncthreads();
        if (t < 162) {
            const int col = t;
            uint32_t h2[16];
            #pragma unroll
            for (int j = 0; j < 16; j++)
                h2[j] = pack_h2(sm[(2*j)*163 + col], sm[(2*j+1)*163 + col]);
            uint4* d = (uint4*)&g_xin[(((size_t)b*XROWS + row)*XCOLS + col)*64 + 32];
            d[0] = make_uint4(h2[0],  h2[1],  h2[2],  h2[3]);
            d[1] = make_uint4(h2[4],  h2[5],  h2[6],  h2[7]);
            d[2] = make_uint4(h2[8],  h2[9],  h2[10], h2[11]);
            d[3] = make_uint4(h2[12], h2[13], h2[14], h2[15]);
        }
    }
}

// ---------------------------------------------------------------------------
// conv1 implicit GEMM fp16 (R8-proven): M=128, N=96, K=144
// ---------------------------------------------------------------------------
__device__ __forceinline__ void load_slice1(int s, uint32_t ab, uint32_t bb,
                                            const __half* x1_b, int y0, int x0, int tid) {
    const int ky = s / 3, kx = s - 3*ky;
    {
        int r = tid >> 1, c = tid & 1;
        int y = y0 + (r >> 5), x = x0 + (r & 31);
        const __half* src = x1_b + ((size_t)(2*y + ky)*X1C + (2*x + kx))*16 + c*8;
        cp16(ab + (uint32_t)(r*(C1STR*2) + c*16), src);
    }
    if (tid < 192) {
        int r = tid >> 1, c = tid & 1;
        const __half* src = g_w1 + (size_t)s*1536 + r*16 + c*8;
        cp16(bb + (uint32_t)(r*(C1STR*2) + c*16), src);
    }
}

__global__ __launch_bounds__(256) void conv1_mma(const float* __restrict__ cb) {
    extern __shared__ __align__(16) float smem[];
    __half* hb = (__half*)smem;
    float* gates1 = smem;

    const uint32_t su = smem_u32(smem);
    const int tid = threadIdx.x;
    const int lane = tid & 31, wid = tid >> 5;
    const int warp_m = wid & 3, warp_n = wid >> 2;
    const int tile = blockIdx.x, b = blockIdx.y;
    const int y0 = (tile / 5) * 4, x0 = (tile % 5) * 32;

    const __half* x1_b = g_x1 + (size_t)b * X1R * X1C * 16;

    float acc[2][6][4] = {};

    load_slice1(0, su,        su + 12288, x1_b, y0, x0, tid); CP_COMMIT();
    load_slice1(1, su + 6144, su + 16896, x1_b, y0, x0, tid); CP_COMMIT();

    const int qr = lane >> 2, qc = lane & 3;

    for (int s = 0; s < 9; s++) {
        const int buf = s & 1;
        CP_WAIT1();
        __syncthreads();

        const __half* Ah = hb + buf*A1SLICE + warp_m*32*C1STR;
        const __half* Bh = hb + 2*A1SLICE + buf*B1SLICE + warp_n*48*C1STR;

        uint32_t af[2][4], bf[6][2];
        #pragma unroll
        for (int mt = 0; mt < 2; mt++) {
            const __half* ap = Ah + (mt*16 + qr)*C1STR + 2*qc;
            af[mt][0] = ldh2(ap);
            af[mt][1] = ldh2(ap + 8*C1STR);
            af[mt][2] = ldh2(ap + 8);
            af[mt][3] = ldh2(ap + 8*C1STR + 8);
        }
        #pragma unroll
        for (int nt = 0; nt < 6; nt++) {
            const __half* bp = Bh + (nt*8 + qr)*C1STR + 2*qc;
            bf[nt][0] = ldh2(bp);
            bf[nt][1] = ldh2(bp + 8);
        }
        #pragma unroll
        for (int mt = 0; mt < 2; mt++)
            #pragma unroll
            for (int nt = 0; nt < 6; nt++)
                mma16816(acc[mt][nt], af[mt], bf[nt]);

        __syncthreads();
        if (s + 2 < 9)
            load_slice1(s + 2, su + buf*6144, su + 12288 + buf*4608,
                        x1_b, y0, x0, tid);
        CP_COMMIT();
    }

    __syncthreads();
    #pragma unroll
    for (int mt = 0; mt < 2; mt++) {
        int m = warp_m*32 + mt*16 + qr;
        #pragma unroll
        for (int nt = 0; nt < 6; nt++) {
            int n = warp_n*48 + nt*8 + 2*qc;
            gates1[(size_t)n*GSTR2 + m]         = acc[mt][nt][0];
            gates1[(size_t)(n+1)*GSTR2 + m]     = acc[mt][nt][1];
            gates1[(size_t)n*GSTR2 + m + 8]     = acc[mt][nt][2];
            gates1[(size_t)(n+1)*GSTR2 + m + 8] = acc[mt][nt][3];
        }
    }
    __syncthreads();

    if (tid < 128) {
        const int m = tid;
        const int y = y0 + (m >> 5), x = x0 + (m & 31);
        const int v = ((y == 0) ? 2 : 0) | ((x == 0) ? 1 : 0);
        float vals[32];
        #pragma unroll
        for (int n = 0; n < 32; n++)
            vals[n] = tanhf(gates1[(size_t)n*GSTR2 + m] + cb[n]
                            + g_gfc[(b*96 + n)*4 + v]);
        uint32_t h2[16];
        #pragma unroll
        for (int j = 0; j < 16; j++) h2[j] = pack_h2(vals[2*j], vals[2*j+1]);
        uint4* d = (uint4*)&g_xin[(((size_t)b*XROWS + y + 1)*XCOLS + x + 1)*64];
        d[0] = make_uint4(h2[0],  h2[1],  h2[2],  h2[3]);
        d[1] = make_uint4(h2[4],  h2[5],  h2[6],  h2[7]);
        d[2] = make_uint4(h2[8],  h2[9],  h2[10], h2[11]);
        d[3] = make_uint4(h2[12], h2[13], h2[14], h2[15]);
    } else {
        const int idx = tid - 128;
        const int n = 32 + (idx >> 1);
        const int mh = idx & 1;
        const float bn = cb[n];
        const float* gfc_n = &g_gfc[(b*96 + n)*4];
        float sum = 0.0f;
        #pragma unroll 8
        for (int mi = 0; mi < 64; mi++) {
            int m = mh*64 + mi;
            int y = y0 + (m >> 5), x = x0 + (m & 31);
            int v = ((y == 0) ? 2 : 0) | ((x == 0) ? 1 : 0);
            sum += tanhf(gates1[(size_t)n*GSTR2 + m] + bn + gfc_n[v]);
        }
        atomicAdd(&g_gfsum[b*GFC + (n - 32)], sum);
    }
}

// ---------------------------------------------------------------------------
// conv2 implicit GEMM fp16: 64px x 128oc per CTA, 4-stage pipeline,
// ldmatrix fragment loads, fused LSTM epilogue. Grid (320, NB), 256 thr.
// ---------------------------------------------------------------------------
__device__ __forceinline__ void load_slice(int s, uint32_t base,
                                           const __half* xin_b, int y0, int x0, int tid) {
    const int tap = s >> 1, h = s & 1;
    const int ky = tap / 3, kx = tap - ky*3;
    {   // A: 64 px x 4 chunks = 256 cp16
        int r = tid >> 2, c = tid & 3;
        const __half* src = xin_b
            + ((size_t)(y0 + (r >> 5) + ky) * XCOLS + (x0 + (r & 31) + kx)) * 64
            + h*32 + c*8;
        cp16(base + (uint32_t)(r*(C2STR*2) + c*16), src);
    }
    const __half* gw = g_wre + (size_t)s * 4096;
    #pragma unroll
    for (int i = 0; i < 2; i++) {   // B: 128 oc x 4 chunks = 512 cp16
        int cid = tid + 256*i;
        int r = cid >> 2, c = cid & 3;
        cp16(base + 5120u + (uint32_t)(r*(C2STR*2) + c*16), gw + r*32 + c*8);
    }
}

__global__ __launch_bounds__(256, 3) void conv2_mma(
    const float* __restrict__ prev_c, const float* __restrict__ gb,
    float* __restrict__ out)
{
    extern __shared__ __align__(16) float smem[];
    float* gates_s = smem;
    __shared__ float bias_s[128];

    const uint32_t su = smem_u32(smem);
    const int tid = threadIdx.x;
    const int lane = tid & 31, wid = tid >> 5;
    const int warp_m = wid & 1, warp_n = wid >> 1;
    const int tile = blockIdx.x, b = blockIdx.y;
    const int y0 = (tile / 5) * 2, x0 = (tile % 5) * 32;

    if (tid < 128) bias_s[tid] = gb[tid];

    const __half* xin_b = g_xin + (size_t)b * XROWS * XCOLS * 64;

    float acc[2][4][4] = {};

    // 4-stage prologue
    load_slice(0, su,             xin_b, y0, x0, tid); CP_COMMIT();
    load_slice(1, su +   SLICE2B, xin_b, y0, x0, tid); CP_COMMIT();
    load_slice(2, su + 2*SLICE2B, xin_b, y0, x0, tid); CP_COMMIT();
    load_slice(3, su + 3*SLICE2B, xin_b, y0, x0, tid); CP_COMMIT();

    // ldmatrix per-lane offsets (bytes)
    //   A: mat = lane>>3 -> row group = mat&1 (0/+8), k half = mat>>1 (0/+8 halves)
    //   B: mat -> n group = mat>>1, k half = mat&1
    const int mat = lane >> 3, mr = lane & 7;
    const uint32_t a_off = (uint32_t)(((warp_m*32 + (mat & 1)*8 + mr)*C2STR
                                       + (mat >> 1)*8) * 2);
    const uint32_t b_off = 5120u + (uint32_t)(((warp_n*32 + (mat >> 1)*8 + mr)*C2STR
                                       + (mat & 1)*8) * 2);

    for (int s = 0; s < 18; s++) {
        const uint32_t stg = su + (uint32_t)((s & 3) * SLICE2B);
        CP_WAIT3();
        __syncthreads();

        uint32_t af[2][2][4];          // [mt][kc][4]
        uint32_t bp[2][2][4];          // [pair][kc][{ntlo b0,b1, nthi b0,b1}]
        LDSM4(af[0][0], stg + a_off);
        LDSM4(af[0][1], stg + a_off + 32);
        LDSM4(af[1][0], stg + a_off + 1280);
        LDSM4(af[1][1], stg + a_off + 1312);
        LDSM4(bp[0][0], stg + b_off);
        LDSM4(bp[0][1], stg + b_off + 32);
        LDSM4(bp[1][0], stg + b_off + 1280);
        LDSM4(bp[1][1], stg + b_off + 1312);

        #pragma unroll
        for (int mt = 0; mt < 2; mt++)
            #pragma unroll
            for (int nt = 0; nt < 4; nt++)
                #pragma unroll
                for (int kc = 0; kc < 2; kc++)
                    mma16816(acc[mt][nt], af[mt][kc], &bp[nt >> 1][kc][(nt & 1)*2]);

        __syncthreads();
        if (s + 4 < 18)
            load_slice(s + 4, su + (uint32_t)((s & 3) * SLICE2B), xin_b, y0, x0, tid);
        CP_COMMIT();
    }

    // ---- epilogue: accums -> smem [n][m] (m=64 px), fused LSTM ----
    const int qr = lane >> 2, qc = lane & 3;
    __syncthreads();
    #pragma unroll
    for (int mt = 0; mt < 2; mt++) {
        int m = warp_m*32 + mt*16 + qr;
        #pragma unroll
        for (int nt = 0; nt < 4; nt++) {
            int n = warp_n*32 + nt*8 + 2*qc;
            gates_s[(size_t)n*GM2 + m]         = acc[mt][nt][0];
            gates_s[(size_t)(n+1)*GM2 + m]     = acc[mt][nt][1];
            gates_s[(size_t)n*GM2 + m + 8]     = acc[mt][nt][2];
            gates_s[(size_t)(n+1)*GM2 + m + 8] = acc[mt][nt][3];
        }
    }
    __syncthreads();

    {   // 256 threads: px = tid>>2 (0..63), 8 oc each
        const int m = tid >> 2;
        const int j0 = (tid & 3) * 8;
        const int y = y0 + (m >> 5), x = x0 + (m & 31);
        #pragma unroll
        for (int i = 0; i < 8; i++) {
            const int j = j0 + i;
            float ig = gates_s[(size_t)(j     )*GM2 + m] + bias_s[j];
            float rg = gates_s[(size_t)(j + 32)*GM2 + m] + bias_s[32 + j];
            float og = gates_s[(size_t)(j + 64)*GM2 + m] + bias_s[64 + j];
            float cg = gates_s[(size_t)(j + 96)*GM2 + m] + bias_s[96 + j];
            size_t hc = (((size_t)b*OUT_CH + j)*HFULL2 + y)*WFULL2 + EX2 + x;
            float pc = prev_c[hc];
            float cell = sigf(rg)*pc + sigf(ig)*tanhf(cg);
            float hid  = sigf(og)*tanhf(cell);
            out[(((size_t)b*OUT_CH + j)*OH + y)*OW + x] = hid;
            out[OFF_H + hc] = hid;
            out[OFF_C + hc] = cell;
        }
    }
}

// ---------------------------------------------------------------------------
// new_gf
// ---------------------------------------------------------------------------
__global__ void gf_kernel(const float* __restrict__ gf, float* __restrict__ out) {
    int i = threadIdx.x;
    out[OFF_GF + i] = tanhf(gf[i] + g_gfsum[i] * (1.0f / (float)(OH*OW)));
}

// ---------------------------------------------------------------------------
// copy prev_h/prev_c -> out, skipping the interior region conv2 overwrites
// ---------------------------------------------------------------------------
__global__ void copy_hc(const float* __restrict__ ph, const float* __restrict__ pc,
                        float* __restrict__ out) {
    const int row = blockIdx.x;
    const int plane = blockIdx.y;
    const int t = threadIdx.x;
    if (t >= 80) return;
    if (row < 128 && t >= 16 && t < 56) return;
    size_t off = ((size_t)plane*HFULL2 + row)*WFULL2 + t*4;
    float4 vh = *(const float4*)(ph + off);
    float4 vc = *(const float4*)(pc + off);
    *(float4*)(out + OFF_H + off) = vh;
    *(float4*)(out + OFF_C + off) = vc;
}

// ---------------------------------------------------------------------------
// Launch: prep_all(1), transforms(2), conv1(3), conv2(4 <- profiled), gf, copy
// ---------------------------------------------------------------------------
extern "C" void kernel_launch(void* const* d_in, const int* in_sizes, int n_in,
                              void* d_out, int out_size) {
    const float* x       = (const float*)d_in[0];
    const float* prev_h  = (const float*)d_in[1];
    const float* prev_c  = (const float*)d_in[2];
    const float* gf      = (const float*)d_in[3];
    const float* conv_w  = (const float*)d_in[4];
    const float* conv_b  = (const float*)d_in[5];
    const float* gates_w = (const float*)d_in[6];
    const float* gates_b = (const float*)d_in[7];
    float* out = (float*)d_out;

    const int stage2 = 4 * SLICE2B;                               // 61440
    const int gates2 = 128 * GM2 * (int)sizeof(float);            // 33280
    const int smem2 = stage2 > gates2 ? stage2 : gates2;          // 61440
    const int smem1 = 96 * GSTR2 * (int)sizeof(float);            // 49536
    cudaFuncSetAttribute(conv2_mma, cudaFuncAttributeMaxDynamicSharedMemorySize, smem2);
    cudaFuncSetAttribute(conv1_mma, cudaFuncAttributeMaxDynamicSharedMemorySize, smem1);

    prep_all<<<dim3(288, 4), 256>>>(gf, conv_w, gates_w);
    transforms<<<dim3(256, NB, 2), 320>>>(x, prev_h);
    conv1_mma<<<dim3(160, NB), 256, smem1>>>(conv_b);
    conv2_mma<<<dim3(320, NB), 256, smem2>>>(prev_c, gates_b, out);
    gf_kernel<<<1, NB*GFC>>>(gf, out);
    copy_hc<<<dim3(HFULL2, NB*OUT_CH), 128>>>(prev_h, prev_c, out);
}